// round 1
// baseline (speedup 1.0000x reference)
#include <cuda_runtime.h>
#include <cstdint>
#include <cstddef>

// ---------------------------------------------------------------------------
// RSSM scan: B=256, T=64, A=64, E=1024, HID=1024, DET=2048, STO=256
// Outputs (concatenated fp32): h[B,T,2048], z, pm, ps, qm, qs (each [B,T,256])
// ---------------------------------------------------------------------------

#define Bv   256
#define Tv   64
#define BTv  (Bv*Tv)          // 16384
#define Av   64
#define Ev   1024
#define HIDv 1024
#define DETv 2048
#define STOv 256

// ------------------------- device scratch (no allocs) ----------------------
__device__ float g_Pobs[BTv * HIDv];    // obs @ W_post_in[DET:] + b_post_in  (64MB)
__device__ float g_rnn [Bv * HIDv];
__device__ float g_gi  [Bv * 3 * DETv];
__device__ float g_gh  [Bv * 3 * DETv];
__device__ float g_pf  [Bv * HIDv];
__device__ float g_rf  [Bv * HIDv];
__device__ float g_zero[Bv * DETv];     // stays zero (zero-initialized)

// ------------------------------- helpers -----------------------------------
__device__ __forceinline__ float to_tf32(float x) {
    uint32_t u;
    asm("cvt.rna.tf32.f32 %0, %1;" : "=r"(u) : "f"(x));
    return __uint_as_float(u);
}

__device__ __forceinline__ void mma8(float c[4], const uint32_t a[4], const uint32_t b[2]) {
    asm volatile(
        "mma.sync.aligned.m16n8k8.row.col.f32.tf32.tf32.f32 "
        "{%0,%1,%2,%3},{%4,%5,%6,%7},{%8,%9},{%0,%1,%2,%3};\n"
        : "+f"(c[0]), "+f"(c[1]), "+f"(c[2]), "+f"(c[3])
        : "r"(a[0]), "r"(a[1]), "r"(a[2]), "r"(a[3]), "r"(b[0]), "r"(b[1]));
}

__device__ __forceinline__ float softplusf(float x) {
    return (x > 20.f) ? x : log1pf(expf(x));
}
__device__ __forceinline__ float sigmoidf(float x) {
    return 1.f / (1.f + expf(-x));
}

// ------------------------------- GEMM --------------------------------------
// C[M,N] = A[M,K] * B  (+epilogue).  A row-major (lda), optionally split in K
// into (A: k<Ksplit, lda) and (A2: k>=Ksplit, lda2).
// B layout: BNK=false -> B[k*ldb + n] ; BNK=true -> B[n*ldb + k]
// Tiles: CTA 128x64, BK=16, 256 threads (8 warps, 4x2 warp grid, 32x32/warp),
// tf32 mma m16n8k8, register double buffering into 2x smem buffers.

struct GemmP {
    const float* A;   int lda;
    const float* A2;  int lda2; int Ksplit;
    const float* B;   int ldb;
    const float* bias;                 // BIAS / MEANSTD
    const float* add; int add_stride;  // RELU_ADD: add[m*stride + n] (stride 0 => bias bcast)
    float* C;  int ldc;
    float* C2;                         // MEANSTD: std output
    int K;
};

enum { EPI_STORE = 0, EPI_BIAS = 1, EPI_RELU_ADD = 2, EPI_MEANSTD = 3 };

template <int EPI, bool SPLITA, bool BNK>
__global__ __launch_bounds__(256)
void gemm_k(GemmP p0, GemmP p1) {
    GemmP p = (blockIdx.z == 0) ? p0 : p1;

    const int tid  = threadIdx.x;
    const int lane = tid & 31, w = tid >> 5;
    const int wm = w >> 1, wn = w & 1;            // 4 x 2 warps
    const int g  = lane >> 2, tig = lane & 3;
    const int bm0 = blockIdx.y * 128, bn0 = blockIdx.x * 64;

    __shared__ __align__(16) float As[2][16][132];
    __shared__ __align__(16) float Bs[2][16][68];

    float acc[2][4][4];
#pragma unroll
    for (int i = 0; i < 2; i++)
#pragma unroll
        for (int j = 0; j < 4; j++)
#pragma unroll
            for (int c = 0; c < 4; c++) acc[i][j][c] = 0.f;

    const int ar = tid >> 1;      // A row in tile (0..127), 2 float4 per thread
    float4 ra[2];
    float4 rbv;

    auto gload = [&](int k0) {
#pragma unroll
        for (int i = 0; i < 2; i++) {
            int kg = k0 + ((tid & 1) + 2 * i) * 4;
            const float* src;
            if (SPLITA && kg >= p.Ksplit)
                src = p.A2 + (size_t)(bm0 + ar) * p.lda2 + (kg - p.Ksplit);
            else
                src = p.A + (size_t)(bm0 + ar) * p.lda + kg;
            ra[i] = *reinterpret_cast<const float4*>(src);
        }
        if (!BNK) {
            rbv = *reinterpret_cast<const float4*>(
                p.B + (size_t)(k0 + (tid >> 4)) * p.ldb + bn0 + (tid & 15) * 4);
        } else {
            rbv = *reinterpret_cast<const float4*>(
                p.B + (size_t)(bn0 + (tid >> 2)) * p.ldb + k0 + (tid & 3) * 4);
        }
    };

    auto sstore = [&](int buf) {
#pragma unroll
        for (int i = 0; i < 2; i++) {
            int kc = ((tid & 1) + 2 * i) * 4;
            As[buf][kc + 0][ar] = to_tf32(ra[i].x);
            As[buf][kc + 1][ar] = to_tf32(ra[i].y);
            As[buf][kc + 2][ar] = to_tf32(ra[i].z);
            As[buf][kc + 3][ar] = to_tf32(ra[i].w);
        }
        if (!BNK) {
            float4 cv;
            cv.x = to_tf32(rbv.x); cv.y = to_tf32(rbv.y);
            cv.z = to_tf32(rbv.z); cv.w = to_tf32(rbv.w);
            *reinterpret_cast<float4*>(&Bs[buf][tid >> 4][(tid & 15) * 4]) = cv;
        } else {
            int kc = (tid & 3) * 4, nr = tid >> 2;
            Bs[buf][kc + 0][nr] = to_tf32(rbv.x);
            Bs[buf][kc + 1][nr] = to_tf32(rbv.y);
            Bs[buf][kc + 2][nr] = to_tf32(rbv.z);
            Bs[buf][kc + 3][nr] = to_tf32(rbv.w);
        }
    };

    auto compute = [&](int buf) {
#pragma unroll
        for (int kk = 0; kk < 16; kk += 8) {
            uint32_t af[2][4], bf[4][2];
#pragma unroll
            for (int mf = 0; mf < 2; mf++) {
                int mr = wm * 32 + mf * 16 + g;
                af[mf][0] = __float_as_uint(As[buf][kk + tig][mr]);
                af[mf][1] = __float_as_uint(As[buf][kk + tig][mr + 8]);
                af[mf][2] = __float_as_uint(As[buf][kk + tig + 4][mr]);
                af[mf][3] = __float_as_uint(As[buf][kk + tig + 4][mr + 8]);
            }
#pragma unroll
            for (int nf = 0; nf < 4; nf++) {
                int nc = wn * 32 + nf * 8 + g;
                bf[nf][0] = __float_as_uint(Bs[buf][kk + tig][nc]);
                bf[nf][1] = __float_as_uint(Bs[buf][kk + tig + 4][nc]);
            }
#pragma unroll
            for (int mf = 0; mf < 2; mf++)
#pragma unroll
                for (int nf = 0; nf < 4; nf++) mma8(acc[mf][nf], af[mf], bf[nf]);
        }
    };

    const int nk = p.K / 16;
    gload(0);
    sstore(0);
    __syncthreads();
    for (int kt = 0; kt < nk; kt++) {
        if (kt + 1 < nk) gload((kt + 1) * 16);
        compute(kt & 1);
        if (kt + 1 < nk) sstore((kt + 1) & 1);
        __syncthreads();
    }

    // epilogue
#pragma unroll
    for (int mf = 0; mf < 2; mf++)
#pragma unroll
        for (int nf = 0; nf < 4; nf++)
#pragma unroll
            for (int cc = 0; cc < 4; cc++) {
                int row = bm0 + wm * 32 + mf * 16 + g + ((cc & 2) ? 8 : 0);
                int col = bn0 + wn * 32 + nf * 8 + tig * 2 + (cc & 1);
                float v = acc[mf][nf][cc];
                if (EPI == EPI_STORE) {
                    p.C[(size_t)row * p.ldc + col] = v;
                } else if (EPI == EPI_BIAS) {
                    p.C[(size_t)row * p.ldc + col] = v + p.bias[col];
                } else if (EPI == EPI_RELU_ADD) {
                    v += p.add[(size_t)row * p.add_stride + col];
                    p.C[(size_t)row * p.ldc + col] = fmaxf(v, 0.f);
                } else { // EPI_MEANSTD: first 256 cols mean, next 256 softplus+0.1
                    v += p.bias[col];
                    if (col < 256)
                        p.C[(size_t)row * p.ldc + col] = v;
                    else
                        p.C2[(size_t)row * p.ldc + (col - 256)] = softplusf(v) + 0.1f;
                }
            }
}

// ------------------------- elementwise kernels ------------------------------
__global__ void gru_k(const float* __restrict__ gi, const float* __restrict__ gh,
                      const float* __restrict__ bih, const float* __restrict__ bhh,
                      const float* __restrict__ hp, int hps,
                      float* __restrict__ h, int hs) {
    int idx = blockIdx.x * blockDim.x + threadIdx.x;    // 256*2048 threads
    int m = idx >> 11, j = idx & 2047;
    size_t base = (size_t)m * 6144;
    float r = sigmoidf(gi[base + j] + bih[j] + gh[base + j] + bhh[j]);
    float u = sigmoidf(gi[base + 2048 + j] + bih[2048 + j] +
                       gh[base + 2048 + j] + bhh[2048 + j]);
    float n = tanhf(gi[base + 4096 + j] + bih[4096 + j] +
                    r * (gh[base + 4096 + j] + bhh[4096 + j]));
    float hprev = hp[(size_t)m * hps + j];
    h[(size_t)m * hs + j] = (1.f - u) * n + u * hprev;
}

__global__ void zsample_k(const float* __restrict__ pm, const float* __restrict__ ps,
                          const float* __restrict__ eps, float* __restrict__ z) {
    size_t off = (size_t)blockIdx.x * (Tv * STOv) + threadIdx.x; // m stride T*256
    z[off] = pm[off] + ps[off] * eps[off];
}

// ------------------------------- launch -------------------------------------
extern "C" void kernel_launch(void* const* d_in, const int* in_sizes, int n_in,
                              void* d_out, int out_size) {
    const float* obs      = (const float*)d_in[0];
    const float* act      = (const float*)d_in[1];
    const float* noise    = (const float*)d_in[4];
    const float* Wrnn     = (const float*)d_in[5];
    const float* brnn     = (const float*)d_in[6];
    const float* Wih      = (const float*)d_in[7];
    const float* Whh      = (const float*)d_in[8];
    const float* bih      = (const float*)d_in[9];
    const float* bhh      = (const float*)d_in[10];
    const float* Wpost_in = (const float*)d_in[11];
    const float* bpost_in = (const float*)d_in[12];
    const float* Wpost_ms = (const float*)d_in[13];
    const float* bpost_ms = (const float*)d_in[14];
    const float* Wprior_in= (const float*)d_in[15];
    const float* bprior_in= (const float*)d_in[16];
    const float* Wprior_ms= (const float*)d_in[17];
    const float* bprior_ms= (const float*)d_in[18];

    float *Pobs, *rnn, *gi, *gh, *pf, *rf, *zerop;
    cudaGetSymbolAddress((void**)&Pobs,  g_Pobs);
    cudaGetSymbolAddress((void**)&rnn,   g_rnn);
    cudaGetSymbolAddress((void**)&gi,    g_gi);
    cudaGetSymbolAddress((void**)&gh,    g_gh);
    cudaGetSymbolAddress((void**)&pf,    g_pf);
    cudaGetSymbolAddress((void**)&rf,    g_rf);
    cudaGetSymbolAddress((void**)&zerop, g_zero);

    float* out  = (float*)d_out;
    float* h_o  = out;
    float* z_o  = h_o + (size_t)BTv * DETv;
    float* pm_o = z_o + (size_t)BTv * STOv;
    float* ps_o = pm_o + (size_t)BTv * STOv;
    float* qm_o = ps_o + (size_t)BTv * STOv;
    float* qs_o = qm_o + (size_t)BTv * STOv;

    // ---- precompute: P_obs = obs @ W_post_in[DET:] + b_post_in  [16384,1024]
    {
        GemmP p{};
        p.A = obs; p.lda = Ev;
        p.B = Wpost_in + (size_t)DETv * HIDv; p.ldb = HIDv;
        p.bias = bpost_in;
        p.C = Pobs; p.ldc = HIDv;
        p.K = Ev;
        gemm_k<EPI_BIAS, false, false><<<dim3(HIDv / 64, BTv / 128, 1), 256>>>(p, p);
    }

    for (int t = 0; t < Tv; t++) {
        // ---- K1: rnn_in = relu([z_prev, a_prev] @ W_rnn_in + b_rnn_in)
        {
            GemmP p{};
            p.A    = t ? z_o + (size_t)(t - 1) * STOv : zerop;
            p.lda  = t ? Tv * STOv : STOv;
            p.A2   = t ? act + (size_t)(t - 1) * Av : zerop;
            p.lda2 = t ? Tv * Av : Av;
            p.Ksplit = STOv; p.K = STOv + Av;      // 320
            p.B = Wrnn; p.ldb = HIDv;
            p.add = brnn; p.add_stride = 0;
            p.C = rnn; p.ldc = HIDv;
            gemm_k<EPI_RELU_ADD, true, false><<<dim3(HIDv / 64, 2, 1), 256>>>(p, p);
        }
        // ---- K2: gi = rnn_in @ Wih^T ; gh = h_prev @ Whh^T   (dual via z)
        {
            GemmP pa{}, pb{};
            pa.A = rnn; pa.lda = HIDv; pa.K = HIDv;
            pa.B = Wih; pa.ldb = HIDv;
            pa.C = gi; pa.ldc = 3 * DETv;
            pb.A   = t ? h_o + (size_t)(t - 1) * DETv : zerop;
            pb.lda = t ? Tv * DETv : DETv;
            pb.K = DETv;
            pb.B = Whh; pb.ldb = DETv;
            pb.C = gh; pb.ldc = 3 * DETv;
            gemm_k<EPI_STORE, false, true><<<dim3(3 * DETv / 64, 2, 2), 256>>>(pa, pb);
        }
        // ---- K3: GRU elementwise -> h_seq[:, t]
        {
            const float* hp = t ? h_o + (size_t)(t - 1) * DETv : zerop;
            int hps = t ? Tv * DETv : DETv;
            gru_k<<<(Bv * DETv) / 256, 256>>>(gi, gh, bih, bhh, hp, hps,
                                              h_o + (size_t)t * DETv, Tv * DETv);
        }
        // ---- K4: pf = relu(h @ Wpost_h + P_obs_t) ; rf = relu(h @ Wprior + b)
        {
            GemmP pc{}, pd{};
            pc.A = h_o + (size_t)t * DETv; pc.lda = Tv * DETv; pc.K = DETv;
            pc.B = Wpost_in; pc.ldb = HIDv;
            pc.add = Pobs + (size_t)t * HIDv; pc.add_stride = Tv * HIDv;
            pc.C = pf; pc.ldc = HIDv;
            pd = pc;
            pd.B = Wprior_in;
            pd.add = bprior_in; pd.add_stride = 0;
            pd.C = rf;
            gemm_k<EPI_RELU_ADD, false, false><<<dim3(HIDv / 64, 2, 2), 256>>>(pc, pd);
        }
        // ---- K5: [pm|ps] = pf @ W_post_ms + b ; [qm|qs] = rf @ W_prior_ms + b
        {
            GemmP pe{}, pg{};
            pe.A = pf; pe.lda = HIDv; pe.K = HIDv;
            pe.B = Wpost_ms; pe.ldb = 2 * STOv;
            pe.bias = bpost_ms;
            pe.C  = pm_o + (size_t)t * STOv; pe.ldc = Tv * STOv;
            pe.C2 = ps_o + (size_t)t * STOv;
            pg = pe;
            pg.A = rf;
            pg.B = Wprior_ms;
            pg.bias = bprior_ms;
            pg.C  = qm_o + (size_t)t * STOv;
            pg.C2 = qs_o + (size_t)t * STOv;
            gemm_k<EPI_MEANSTD, false, false><<<dim3(2 * STOv / 64, 2, 2), 256>>>(pe, pg);
        }
        // ---- K6: z = pm + ps * eps
        zsample_k<<<Bv, STOv>>>(pm_o + (size_t)t * STOv, ps_o + (size_t)t * STOv,
                                noise + (size_t)t * STOv, z_o + (size_t)t * STOv);
    }
}

// round 3
// speedup vs baseline: 1.2627x; 1.2627x over previous
#include <cuda_runtime.h>
#include <cstdint>
#include <cstddef>

// ---------------------------------------------------------------------------
// RSSM scan: B=256, T=64, A=64, E=1024, HID=1024, DET=2048, STO=256
// Outputs (concatenated fp32): h[B,T,2048], z, pm, ps, qm, qs (each [B,T,256])
// ---------------------------------------------------------------------------

#define Bv   256
#define Tv   64
#define BTv  (Bv*Tv)          // 16384
#define Av   64
#define Ev   1024
#define HIDv 1024
#define DETv 2048
#define STOv 256

// ------------------------- device scratch (no allocs) ----------------------
__device__ float g_Pobs[BTv * HIDv];    // obs proj; reused as rf after scan (64MB)
__device__ float g_pre [BTv * HIDv];    // action part of rnn_in + bias       (64MB)
__device__ float g_rnn [Bv * HIDv];
__device__ float g_gi  [Bv * 3 * DETv];
__device__ float g_gh  [Bv * 3 * DETv];
__device__ float g_pf  [Bv * HIDv];
__device__ float g_p4  [4 * Bv * HIDv];     // split-K partials for pf
__device__ float g_p5  [4 * Bv * 2 * STOv]; // split-K partials for pm/ps
__device__ float g_zero[DETv];              // stays zero
__device__ unsigned g_barcnt;
__device__ unsigned g_bargen;

// ------------------------------- helpers -----------------------------------
__device__ __forceinline__ float to_tf32(float x) {
    uint32_t u;
    asm("cvt.rna.tf32.f32 %0, %1;" : "=r"(u) : "f"(x));
    return __uint_as_float(u);
}

__device__ __forceinline__ void mma8(float c[4], const uint32_t a[4], const uint32_t b[2]) {
    asm volatile(
        "mma.sync.aligned.m16n8k8.row.col.f32.tf32.tf32.f32 "
        "{%0,%1,%2,%3},{%4,%5,%6,%7},{%8,%9},{%0,%1,%2,%3};\n"
        : "+f"(c[0]), "+f"(c[1]), "+f"(c[2]), "+f"(c[3])
        : "r"(a[0]), "r"(a[1]), "r"(a[2]), "r"(a[3]), "r"(b[0]), "r"(b[1]));
}

__device__ __forceinline__ float softplusf(float x) {
    return (x > 20.f) ? x : log1pf(expf(x));
}
__device__ __forceinline__ float sigmoidf(float x) {
    return 1.f / (1.f + expf(-x));
}

// ---------------------------- grid-wide barrier -----------------------------
__device__ __forceinline__ void gridbar(int nb) {
    __syncthreads();
    if (threadIdx.x == 0) {
        __threadfence();
        unsigned gen;
        asm volatile("ld.acquire.gpu.u32 %0, [%1];" : "=r"(gen) : "l"(&g_bargen) : "memory");
        unsigned arr = atomicAdd(&g_barcnt, 1u);
        if (arr == (unsigned)nb - 1u) {
            atomicExch(&g_barcnt, 0u);
            __threadfence();
            atomicAdd(&g_bargen, 1u);
        } else {
            unsigned cur;
            do {
                asm volatile("ld.acquire.gpu.u32 %0, [%1];" : "=r"(cur) : "l"(&g_bargen) : "memory");
            } while (cur == gen);
        }
        __threadfence();
    }
    __syncthreads();
}

// ------------------------------- GEMM core ----------------------------------
// acc[128x64 tile] += A[M,K] * B. A row-major(lda). BNK=false: B[k*ldb+n];
// BNK=true: B[n*ldb+k]. ROWMASK: rows with (row&63)==0 read zeros (prev-action).
// 256 threads, 8 warps (4x2), 32x32 warp tile, tf32 mma m16n8k8, double buffer.

struct SmemBuf {
    float As[2][16][132];
    float Bs[2][16][68];
};

template <bool BNK, bool ROWMASK>
__device__ __forceinline__ void gemm_acc(const float* __restrict__ A, int lda,
                                         const float* __restrict__ Bp, int ldb,
                                         int K, int bm0, int bn0,
                                         float acc[2][4][4], SmemBuf& sb) {
    const int tid  = threadIdx.x;
    const int lane = tid & 31, w = tid >> 5;
    const int wm = w >> 1, wn = w & 1;
    const int g  = lane >> 2, tig = lane & 3;
    const int ar = tid >> 1;

#pragma unroll
    for (int i = 0; i < 2; i++)
#pragma unroll
        for (int j = 0; j < 4; j++)
#pragma unroll
            for (int c = 0; c < 4; c++) acc[i][j][c] = 0.f;

    float4 ra[2];
    float4 rbv;

    auto gload = [&](int k0) {
        int row = bm0 + ar;
        const float* arow;
        if (ROWMASK && ((row & 63) == 0)) arow = g_zero;
        else arow = A + (size_t)row * lda;
#pragma unroll
        for (int i = 0; i < 2; i++) {
            int kg = k0 + ((tid & 1) + 2 * i) * 4;
            ra[i] = *reinterpret_cast<const float4*>(arow + kg);
        }
        if (!BNK) {
            rbv = *reinterpret_cast<const float4*>(
                Bp + (size_t)(k0 + (tid >> 4)) * ldb + bn0 + (tid & 15) * 4);
        } else {
            rbv = *reinterpret_cast<const float4*>(
                Bp + (size_t)(bn0 + (tid >> 2)) * ldb + k0 + (tid & 3) * 4);
        }
    };

    auto sstore = [&](int buf) {
#pragma unroll
        for (int i = 0; i < 2; i++) {
            int kc = ((tid & 1) + 2 * i) * 4;
            sb.As[buf][kc + 0][ar] = to_tf32(ra[i].x);
            sb.As[buf][kc + 1][ar] = to_tf32(ra[i].y);
            sb.As[buf][kc + 2][ar] = to_tf32(ra[i].z);
            sb.As[buf][kc + 3][ar] = to_tf32(ra[i].w);
        }
        if (!BNK) {
            float4 cv;
            cv.x = to_tf32(rbv.x); cv.y = to_tf32(rbv.y);
            cv.z = to_tf32(rbv.z); cv.w = to_tf32(rbv.w);
            *reinterpret_cast<float4*>(&sb.Bs[buf][tid >> 4][(tid & 15) * 4]) = cv;
        } else {
            int kc = (tid & 3) * 4, nr = tid >> 2;
            sb.Bs[buf][kc + 0][nr] = to_tf32(rbv.x);
            sb.Bs[buf][kc + 1][nr] = to_tf32(rbv.y);
            sb.Bs[buf][kc + 2][nr] = to_tf32(rbv.z);
            sb.Bs[buf][kc + 3][nr] = to_tf32(rbv.w);
        }
    };

    auto compute = [&](int buf) {
#pragma unroll
        for (int kk = 0; kk < 16; kk += 8) {
            uint32_t af[2][4], bf[4][2];
#pragma unroll
            for (int mf = 0; mf < 2; mf++) {
                int mr = wm * 32 + mf * 16 + g;
                af[mf][0] = __float_as_uint(sb.As[buf][kk + tig][mr]);
                af[mf][1] = __float_as_uint(sb.As[buf][kk + tig][mr + 8]);
                af[mf][2] = __float_as_uint(sb.As[buf][kk + tig + 4][mr]);
                af[mf][3] = __float_as_uint(sb.As[buf][kk + tig + 4][mr + 8]);
            }
#pragma unroll
            for (int nf = 0; nf < 4; nf++) {
                int nc = wn * 32 + nf * 8 + g;
                bf[nf][0] = __float_as_uint(sb.Bs[buf][kk + tig][nc]);
                bf[nf][1] = __float_as_uint(sb.Bs[buf][kk + tig + 4][nc]);
            }
#pragma unroll
            for (int mf = 0; mf < 2; mf++)
#pragma unroll
                for (int nf = 0; nf < 4; nf++) mma8(acc[mf][nf], af[mf], bf[nf]);
        }
    };

    const int nk = K / 16;
    gload(0);
    sstore(0);
    __syncthreads();
    for (int kt = 0; kt < nk; kt++) {
        if (kt + 1 < nk) gload((kt + 1) * 16);
        compute(kt & 1);
        if (kt + 1 < nk) sstore((kt + 1) & 1);
        __syncthreads();
    }
}

template <typename F>
__device__ __forceinline__ void epi_apply(int bm0, int bn0, float acc[2][4][4], F&& f) {
    const int tid  = threadIdx.x;
    const int lane = tid & 31, w = tid >> 5;
    const int wm = w >> 1, wn = w & 1;
    const int g  = lane >> 2, tig = lane & 3;
#pragma unroll
    for (int mf = 0; mf < 2; mf++)
#pragma unroll
        for (int nf = 0; nf < 4; nf++)
#pragma unroll
            for (int cc = 0; cc < 4; cc++) {
                int row = bm0 + wm * 32 + mf * 16 + g + ((cc & 2) ? 8 : 0);
                int col = bn0 + wn * 32 + nf * 8 + tig * 2 + (cc & 1);
                f(row, col, acc[mf][nf][cc]);
            }
}

// --------------------------- pre / post kernels -----------------------------
// Pobs = obs @ W_post_in[DET:] + b_post_in  (tiles 0..2047)
// pre  = prev_actions @ W_rnn_in[STO:] + b_rnn_in (tiles 2048..4095, row-masked)
__global__ __launch_bounds__(256)
void prep_k(const float* __restrict__ obs, const float* __restrict__ act,
            const float* __restrict__ Wpost_in, const float* __restrict__ bpost_in,
            const float* __restrict__ Wrnn, const float* __restrict__ brnn) {
    __shared__ SmemBuf sb;
    float acc[2][4][4];
    int tile = blockIdx.x;
    if (tile < 2048) {
        int bm0 = (tile & 127) * 128, bn0 = (tile >> 7) * 64;
        gemm_acc<false, false>(obs, Ev, Wpost_in + (size_t)DETv * HIDv, HIDv, Ev,
                               bm0, bn0, acc, sb);
        epi_apply(bm0, bn0, acc, [&](int r, int c, float v) {
            g_Pobs[(size_t)r * HIDv + c] = v + bpost_in[c];
        });
    } else {
        tile -= 2048;
        int bm0 = (tile & 127) * 128, bn0 = (tile >> 7) * 64;
        gemm_acc<false, true>(act - Av, Av, Wrnn + (size_t)STOv * HIDv, HIDv, Av,
                              bm0, bn0, acc, sb);
        epi_apply(bm0, bn0, acc, [&](int r, int c, float v) {
            g_pre[(size_t)r * HIDv + c] = v + brnn[c];
        });
    }
}

// rf = relu(h_seq @ W_prior_in + b)  -> reuse g_Pobs
__global__ __launch_bounds__(256)
void rf_k(const float* __restrict__ h_o, const float* __restrict__ Wprior_in,
          const float* __restrict__ bprior_in) {
    __shared__ SmemBuf sb;
    float acc[2][4][4];
    int tile = blockIdx.x;
    int bm0 = (tile & 127) * 128, bn0 = (tile >> 7) * 64;
    gemm_acc<false, false>(h_o, DETv, Wprior_in, HIDv, DETv, bm0, bn0, acc, sb);
    epi_apply(bm0, bn0, acc, [&](int r, int c, float v) {
        g_Pobs[(size_t)r * HIDv + c] = fmaxf(v + bprior_in[c], 0.f);
    });
}

// [qm|qs] = rf @ W_prior_ms + b, softplus on std half
__global__ __launch_bounds__(256)
void ms_k(const float* __restrict__ Wprior_ms, const float* __restrict__ bprior_ms,
          float* __restrict__ qm_o, float* __restrict__ qs_o) {
    __shared__ SmemBuf sb;
    float acc[2][4][4];
    int tile = blockIdx.x;
    int bm0 = (tile & 127) * 128, bn0 = (tile >> 7) * 64;
    gemm_acc<false, false>(g_Pobs, HIDv, Wprior_ms, 2 * STOv, HIDv, bm0, bn0, acc, sb);
    epi_apply(bm0, bn0, acc, [&](int r, int c, float v) {
        v += bprior_ms[c];
        if (c < STOv) qm_o[(size_t)r * STOv + c] = v;
        else          qs_o[(size_t)r * STOv + (c - STOv)] = softplusf(v) + 0.1f;
    });
}

// --------------------------- persistent scan kernel -------------------------
struct ScanArgs {
    const float* noise;
    const float* Wrnn;
    const float* Wih; const float* Whh;
    const float* bih; const float* bhh;
    const float* Wpost_in; const float* Wpost_ms; const float* bpost_ms;
    float* h_o; float* z_o; float* pm_o; float* ps_o;
    int nb;
};

__global__ __launch_bounds__(256, 2)
void scan_k(ScanArgs a) {
    __shared__ SmemBuf sb;
    const int nb = a.nb;
    float acc[2][4][4];

    for (int t = 0; t < Tv; t++) {
        // ---- P1: rnn = relu(z_prev @ Wz + pre_t)   (32 tiles, K=256)
        {
            const float* A = t ? a.z_o + (size_t)(t - 1) * STOv : g_zero;
            int lda = t ? Tv * STOv : 0;
            for (int tile = blockIdx.x; tile < 32; tile += nb) {
                int bm0 = (tile & 1) * 128, bn0 = (tile >> 1) * 64;
                gemm_acc<false, false>(A, lda, a.Wrnn, HIDv, STOv, bm0, bn0, acc, sb);
                epi_apply(bm0, bn0, acc, [&](int r, int c, float v) {
                    v += g_pre[((size_t)r * Tv + t) * HIDv + c];
                    g_rnn[(size_t)r * HIDv + c] = fmaxf(v, 0.f);
                });
            }
        }
        gridbar(nb);

        // ---- P2: gi = rnn @ Wih^T + bih (192 tiles, K=1024)
        //          gh = h_prev @ Whh^T + bhh (192 tiles, K=2048)
        {
            const float* Ah = t ? a.h_o + (size_t)(t - 1) * DETv : g_zero;
            int ldah = t ? Tv * DETv : 0;
            for (int tile = blockIdx.x; tile < 384; tile += nb) {
                if (tile < 192) {
                    int bm0 = (tile & 1) * 128, bn0 = (tile >> 1) * 64;
                    gemm_acc<true, false>(g_rnn, HIDv, a.Wih, HIDv, HIDv, bm0, bn0, acc, sb);
                    epi_apply(bm0, bn0, acc, [&](int r, int c, float v) {
                        g_gi[(size_t)r * (3 * DETv) + c] = v + a.bih[c];
                    });
                } else {
                    int tt = tile - 192;
                    int bm0 = (tt & 1) * 128, bn0 = (tt >> 1) * 64;
                    gemm_acc<true, false>(Ah, ldah, a.Whh, DETv, DETv, bm0, bn0, acc, sb);
                    epi_apply(bm0, bn0, acc, [&](int r, int c, float v) {
                        g_gh[(size_t)r * (3 * DETv) + c] = v + a.bhh[c];
                    });
                }
            }
        }
        gridbar(nb);

        // ---- P3: GRU elementwise -> h_t
        {
            const float* hp = t ? a.h_o + (size_t)(t - 1) * DETv : g_zero;
            int hps = t ? Tv * DETv : 0;
            for (int i = blockIdx.x * 256 + threadIdx.x; i < Bv * DETv; i += nb * 256) {
                int m = i >> 11, j = i & 2047;
                size_t base = (size_t)m * (3 * DETv);
                float r = sigmoidf(g_gi[base + j] + g_gh[base + j]);
                float u = sigmoidf(g_gi[base + DETv + j] + g_gh[base + DETv + j]);
                float n = tanhf(g_gi[base + 2 * DETv + j] + r * g_gh[base + 2 * DETv + j]);
                float hv = (1.f - u) * n + u * hp[(size_t)m * hps + j];
                a.h_o[((size_t)m * Tv + t) * DETv + j] = hv;
            }
        }
        gridbar(nb);

        // ---- P4a: pf split-K partials (128 tiles: 4 ksplit x 32, K=512)
        for (int tile = blockIdx.x; tile < 128; tile += nb) {
            int ks = tile >> 5, rem = tile & 31;
            int bm0 = (rem & 1) * 128, bn0 = (rem >> 1) * 64;
            gemm_acc<false, false>(a.h_o + (size_t)t * DETv + ks * 512, Tv * DETv,
                                   a.Wpost_in + (size_t)ks * 512 * HIDv, HIDv, 512,
                                   bm0, bn0, acc, sb);
            epi_apply(bm0, bn0, acc, [&](int r, int c, float v) {
                g_p4[(size_t)ks * Bv * HIDv + (size_t)r * HIDv + c] = v;
            });
        }
        gridbar(nb);

        // ---- P4b: reduce + Pobs + relu -> pf
        for (int i = blockIdx.x * 256 + threadIdx.x; i < Bv * HIDv; i += nb * 256) {
            int m = i >> 10, j = i & 1023;
            float v = g_p4[i] + g_p4[(size_t)Bv * HIDv + i] +
                      g_p4[2 * (size_t)Bv * HIDv + i] + g_p4[3 * (size_t)Bv * HIDv + i];
            v += g_Pobs[((size_t)m * Tv + t) * HIDv + j];
            g_pf[i] = fmaxf(v, 0.f);
        }
        gridbar(nb);

        // ---- P5a: [pm|ps] split-K partials (64 tiles: 4 ksplit x 2m x 8n, K=256)
        for (int tile = blockIdx.x; tile < 64; tile += nb) {
            int ks = tile >> 4, rem = tile & 15;
            int bm0 = (rem & 1) * 128, bn0 = (rem >> 1) * 64;
            gemm_acc<false, false>(g_pf + ks * 256, HIDv,
                                   a.Wpost_ms + (size_t)ks * 256 * (2 * STOv), 2 * STOv,
                                   256, bm0, bn0, acc, sb);
            epi_apply(bm0, bn0, acc, [&](int r, int c, float v) {
                g_p5[(size_t)ks * Bv * (2 * STOv) + (size_t)r * (2 * STOv) + c] = v;
            });
        }
        gridbar(nb);

        // ---- P5b: pm, ps, z
        for (int i = blockIdx.x * 256 + threadIdx.x; i < Bv * STOv; i += nb * 256) {
            int m = i >> 8, j = i & 255;
            size_t b0 = (size_t)m * (2 * STOv);
            const size_t S = (size_t)Bv * (2 * STOv);
            float pm = g_p5[b0 + j] + g_p5[S + b0 + j] + g_p5[2 * S + b0 + j] +
                       g_p5[3 * S + b0 + j] + a.bpost_ms[j];
            float sr = g_p5[b0 + STOv + j] + g_p5[S + b0 + STOv + j] +
                       g_p5[2 * S + b0 + STOv + j] + g_p5[3 * S + b0 + STOv + j] +
                       a.bpost_ms[STOv + j];
            float ps = softplusf(sr) + 0.1f;
            size_t o = ((size_t)m * Tv + t) * STOv + j;
            a.pm_o[o] = pm;
            a.ps_o[o] = ps;
            a.z_o[o] = pm + ps * a.noise[o];
        }
        gridbar(nb);
    }
}

// ------------------------------- launch -------------------------------------
extern "C" void kernel_launch(void* const* d_in, const int* in_sizes, int n_in,
                              void* d_out, int out_size) {
    const float* obs      = (const float*)d_in[0];
    const float* act      = (const float*)d_in[1];
    const float* noise    = (const float*)d_in[4];
    const float* Wrnn     = (const float*)d_in[5];
    const float* brnn     = (const float*)d_in[6];
    const float* Wih      = (const float*)d_in[7];
    const float* Whh      = (const float*)d_in[8];
    const float* bih      = (const float*)d_in[9];
    const float* bhh      = (const float*)d_in[10];
    const float* Wpost_in = (const float*)d_in[11];
    const float* bpost_in = (const float*)d_in[12];
    const float* Wpost_ms = (const float*)d_in[13];
    const float* bpost_ms = (const float*)d_in[14];
    const float* Wprior_in= (const float*)d_in[15];
    const float* bprior_in= (const float*)d_in[16];
    const float* Wprior_ms= (const float*)d_in[17];
    const float* bprior_ms= (const float*)d_in[18];

    float* out  = (float*)d_out;
    float* h_o  = out;
    float* z_o  = h_o + (size_t)BTv * DETv;
    float* pm_o = z_o + (size_t)BTv * STOv;
    float* ps_o = pm_o + (size_t)BTv * STOv;
    float* qm_o = ps_o + (size_t)BTv * STOv;
    float* qs_o = qm_o + (size_t)BTv * STOv;

    int nsm = 0, maxb = 0;
    cudaDeviceGetAttribute(&nsm, cudaDevAttrMultiProcessorCount, 0);
    cudaOccupancyMaxActiveBlocksPerMultiprocessor(&maxb, scan_k, 256, 0);
    if (maxb > 2) maxb = 2;
    if (maxb < 1) maxb = 1;
    int nb = nsm * maxb;

    // 1) batched precompute: Pobs + action-part of rnn_in
    prep_k<<<4096, 256>>>(obs, act, Wpost_in, bpost_in, Wrnn, brnn);

    // 2) persistent 64-step scan
    ScanArgs a;
    a.noise = noise; a.Wrnn = Wrnn;
    a.Wih = Wih; a.Whh = Whh; a.bih = bih; a.bhh = bhh;
    a.Wpost_in = Wpost_in; a.Wpost_ms = Wpost_ms; a.bpost_ms = bpost_ms;
    a.h_o = h_o; a.z_o = z_o; a.pm_o = pm_o; a.ps_o = ps_o;
    a.nb = nb;
    scan_k<<<nb, 256>>>(a);

    // 3) batched prior: rf then qm/qs
    rf_k<<<2048, 256>>>(h_o, Wprior_in, bprior_in);
    ms_k<<<1024, 256>>>(Wprior_ms, bprior_ms, qm_o, qs_o);
}

// round 5
// speedup vs baseline: 2.0655x; 1.6358x over previous
#include <cuda_runtime.h>
#include <cstdint>
#include <cstddef>

// ---------------------------------------------------------------------------
// RSSM scan: B=256, T=64, A=64, E=1024, HID=1024, DET=2048, STO=256
// mma.sync tf32 core with 4-stage cp.async pipeline; persistent scan kernel.
// ---------------------------------------------------------------------------

#define Bv   256
#define Tv   64
#define BTv  (Bv*Tv)          // 16384
#define Av   64
#define Ev   1024
#define HIDv 1024
#define DETv 2048
#define STOv 256

#define BM 128
#define BN 64
#define BK 16
#define NSTAGE 4
#define ASTR 20               // padded row stride (floats) -> conflict-free frags
#define DYN_SMEM (NSTAGE * (BM * ASTR + BN * ASTR) * 4)   // 61440 B

// ------------------------- device scratch (no allocs) ----------------------
__device__ __align__(16) float g_Pobs[BTv * HIDv];    // obs proj; reused as rf later
__device__ __align__(16) float g_pre [BTv * HIDv];    // action part of rnn_in + bias
__device__ __align__(16) float g_rnn [Bv * HIDv];
__device__ __align__(16) float g_gi  [Bv * 3 * DETv];
__device__ __align__(16) float g_gh  [Bv * 3 * DETv];
__device__ __align__(16) float g_pf  [Bv * HIDv];
__device__ __align__(16) float g_p4  [4 * Bv * HIDv];
__device__ __align__(16) float g_p5  [4 * Bv * 2 * STOv];
__device__ __align__(16) float g_zero[DETv];          // stays zero
// pre-rounded (tf32) weights, all stored [N,K] row-major (K contiguous)
__device__ __align__(16) float g_WrnnT    [HIDv * (STOv + Av)];
__device__ __align__(16) float g_WpostT   [HIDv * (DETv + Ev)];
__device__ __align__(16) float g_WpostmsT [2 * STOv * HIDv];
__device__ __align__(16) float g_WpriorT  [HIDv * DETv];
__device__ __align__(16) float g_WpriormsT[2 * STOv * HIDv];
__device__ __align__(16) float g_WihR     [3 * DETv * HIDv];   // already [N,K]
__device__ __align__(16) float g_WhhR     [3 * DETv * DETv];   // already [N,K]
__device__ unsigned g_barcnt;
__device__ unsigned g_bargen;

// ------------------------------- helpers -----------------------------------
__device__ __forceinline__ float to_tf32(float x) {
    uint32_t u;
    asm("cvt.rna.tf32.f32 %0, %1;" : "=r"(u) : "f"(x));
    return __uint_as_float(u);
}
__device__ __forceinline__ uint32_t cvt_tf32(float x) {
    uint32_t u;
    asm("cvt.rna.tf32.f32 %0, %1;" : "=r"(u) : "f"(x));
    return u;
}
__device__ __forceinline__ float softplusf(float x) {
    return (x > 20.f) ? x : log1pf(expf(x));
}
__device__ __forceinline__ float sigmoidf(float x) {
    return 1.f / (1.f + expf(-x));
}
__device__ __forceinline__ uint32_t smem_u32(const void* p) {
    uint32_t a;
    asm("{ .reg .u64 t; cvta.to.shared.u64 t, %1; cvt.u32.u64 %0, t; }"
        : "=r"(a) : "l"(p));
    return a;
}
__device__ __forceinline__ void cpa16(uint32_t dst, const float* src) {
    size_t g = __cvta_generic_to_global((const void*)src);
    asm volatile("cp.async.cg.shared.global [%0], [%1], 16;"
                 :: "r"(dst), "l"(g) : "memory");
}
__device__ __forceinline__ void cpa_commit() {
    asm volatile("cp.async.commit_group;" ::: "memory");
}

__device__ __forceinline__ void mma8(float c[4], const uint32_t a[4], const uint32_t b[2]) {
    asm volatile(
        "mma.sync.aligned.m16n8k8.row.col.f32.tf32.tf32.f32 "
        "{%0,%1,%2,%3},{%4,%5,%6,%7},{%8,%9},{%0,%1,%2,%3};\n"
        : "+f"(c[0]), "+f"(c[1]), "+f"(c[2]), "+f"(c[3])
        : "r"(a[0]), "r"(a[1]), "r"(a[2]), "r"(a[3]), "r"(b[0]), "r"(b[1]));
}

// ---------------------------- grid-wide barrier -----------------------------
__device__ __forceinline__ void gridbar(int nb) {
    __syncthreads();
    if (threadIdx.x == 0) {
        __threadfence();
        unsigned gen;
        asm volatile("ld.acquire.gpu.u32 %0, [%1];" : "=r"(gen) : "l"(&g_bargen) : "memory");
        unsigned arr = atomicAdd(&g_barcnt, 1u);
        if (arr == (unsigned)nb - 1u) {
            atomicExch(&g_barcnt, 0u);
            __threadfence();
            atomicAdd(&g_bargen, 1u);
        } else {
            unsigned cur;
            do {
                asm volatile("ld.acquire.gpu.u32 %0, [%1];" : "=r"(cur) : "l"(&g_bargen) : "memory");
            } while (cur == gen);
        }
        __threadfence();
    }
    __syncthreads();
}

// ------------------------------- GEMM core ----------------------------------
// acc[128x64] = A[M,K](row-major,lda, fp32, cvt in compute) x B[N,K](row-major,
// ldb, PRE-ROUNDED tf32). K mult of 16. ROWMASK: rows with (row&63)==0 -> zeros.
// 256 threads, 8 warps (4x2), 32x32 warp tiles, 4-stage cp.async pipeline.

__device__ __forceinline__ void compute_stage(const float* sa, const float* sb,
                                              float acc[2][4][4]) {
    const int lane = threadIdx.x & 31, w = threadIdx.x >> 5;
    const int wm = w >> 1, wn = w & 1;
    const int g = lane >> 2, tig = lane & 3;
#pragma unroll
    for (int kk = 0; kk < BK; kk += 8) {
        uint32_t af[2][4], bf[4][2];
#pragma unroll
        for (int mf = 0; mf < 2; mf++) {
            int mr = wm * 32 + mf * 16 + g;
            af[mf][0] = cvt_tf32(sa[mr * ASTR + kk + tig]);
            af[mf][1] = cvt_tf32(sa[(mr + 8) * ASTR + kk + tig]);
            af[mf][2] = cvt_tf32(sa[mr * ASTR + kk + tig + 4]);
            af[mf][3] = cvt_tf32(sa[(mr + 8) * ASTR + kk + tig + 4]);
        }
#pragma unroll
        for (int nf = 0; nf < 4; nf++) {
            int nc = wn * 32 + nf * 8 + g;
            bf[nf][0] = __float_as_uint(sb[nc * ASTR + kk + tig]);
            bf[nf][1] = __float_as_uint(sb[nc * ASTR + kk + tig + 4]);
        }
#pragma unroll
        for (int mf = 0; mf < 2; mf++)
#pragma unroll
            for (int nf = 0; nf < 4; nf++) mma8(acc[mf][nf], af[mf], bf[nf]);
    }
}

template <bool ROWMASK>
__device__ void gemm_cp(float* smem, const float* __restrict__ A, int lda,
                        const float* __restrict__ B, int ldb,
                        int K, int bm0, int bn0, float acc[2][4][4]) {
    float* sa = smem;
    float* sb = smem + NSTAGE * BM * ASTR;
    const uint32_t sa_u = smem_u32(sa), sb_u = smem_u32(sb);
    const int tid = threadIdx.x;

#pragma unroll
    for (int i = 0; i < 2; i++)
#pragma unroll
        for (int j = 0; j < 4; j++)
#pragma unroll
            for (int c = 0; c < 4; c++) acc[i][j][c] = 0.f;

    auto load_stage = [&](int s, int k0) {
#pragma unroll
        for (int i = 0; i < 2; i++) {
            int idx = tid + (i << 8);
            int row = idx >> 2, kc = (idx & 3) << 2;
            int grow = bm0 + row;
            const float* src = (ROWMASK && ((grow & 63) == 0))
                                   ? (g_zero + kc)
                                   : (A + (size_t)grow * lda + k0 + kc);
            cpa16(sa_u + (uint32_t)(s * BM * ASTR + row * ASTR + kc) * 4u, src);
        }
        {
            int row = tid >> 2, kc = (tid & 3) << 2;
            cpa16(sb_u + (uint32_t)(s * BN * ASTR + row * ASTR + kc) * 4u,
                  B + (size_t)(bn0 + row) * ldb + k0 + kc);
        }
        cpa_commit();
    };

    const int nk = K >> 4;
#pragma unroll
    for (int s = 0; s < NSTAGE - 1; s++) {
        if (s < nk) load_stage(s, s << 4);
        else cpa_commit();
    }
    for (int kt = 0; kt < nk; kt++) {
        asm volatile("cp.async.wait_group %0;" :: "n"(NSTAGE - 2) : "memory");
        __syncthreads();
        int kn = kt + NSTAGE - 1;
        if (kn < nk) load_stage(kn & (NSTAGE - 1), kn << 4);
        else cpa_commit();
        compute_stage(sa + (kt & (NSTAGE - 1)) * BM * ASTR,
                      sb + (kt & (NSTAGE - 1)) * BN * ASTR, acc);
    }
    __syncthreads();
}

template <typename F>
__device__ __forceinline__ void epi_apply(int bm0, int bn0, float acc[2][4][4], F&& f) {
    const int tid = threadIdx.x;
    const int lane = tid & 31, w = tid >> 5;
    const int wm = w >> 1, wn = w & 1;
    const int g = lane >> 2, tig = lane & 3;
#pragma unroll
    for (int mf = 0; mf < 2; mf++)
#pragma unroll
        for (int nf = 0; nf < 4; nf++)
#pragma unroll
            for (int cc = 0; cc < 4; cc++) {
                int row = bm0 + wm * 32 + mf * 16 + g + ((cc & 2) ? 8 : 0);
                int col = bn0 + wn * 32 + nf * 8 + tig * 2 + (cc & 1);
                f(row, col, acc[mf][nf][cc]);
            }
}

// -------------------------- weight prep kernels ------------------------------
// transpose + round to tf32: dst[C,R] (stride R) = rna(src[R,C])
__global__ __launch_bounds__(256)
void transpose_k(const float* __restrict__ src, float* __restrict__ dst, int R, int C) {
    __shared__ float tile[32][33];
    int rb = blockIdx.x * 32, cb = blockIdx.y * 32;
    int x = threadIdx.x & 31, y = threadIdx.x >> 5;
#pragma unroll
    for (int i = 0; i < 32; i += 8)
        tile[y + i][x] = src[(size_t)(rb + y + i) * C + cb + x];
    __syncthreads();
#pragma unroll
    for (int i = 0; i < 32; i += 8)
        dst[(size_t)(cb + y + i) * R + rb + x] = to_tf32(tile[x][y + i]);
}

__global__ __launch_bounds__(256)
void roundcopy_k(const float* __restrict__ src, float* __restrict__ dst, int n) {
    int i = (blockIdx.x * 256 + threadIdx.x) * 4;
    if (i < n) {
        float4 v = *reinterpret_cast<const float4*>(src + i);
        v.x = to_tf32(v.x); v.y = to_tf32(v.y);
        v.z = to_tf32(v.z); v.w = to_tf32(v.w);
        *reinterpret_cast<float4*>(dst + i) = v;
    }
}

// --------------------------- batched pre / post -----------------------------
__global__ __launch_bounds__(256)
void prep_k(const float* __restrict__ obs, const float* __restrict__ act,
            const float* __restrict__ bpost_in, const float* __restrict__ brnn) {
    extern __shared__ float dyn[];
    float acc[2][4][4];
    int tile = blockIdx.x;
    if (tile < 2048) {   // Pobs = obs @ WpostT[:,2048:]^T + b
        int bm0 = (tile & 127) << 7, bn0 = (tile >> 7) << 6;
        gemm_cp<false>(dyn, obs, Ev, g_WpostT + DETv, DETv + Ev, Ev, bm0, bn0, acc);
        epi_apply(bm0, bn0, acc, [&](int r, int c, float v) {
            g_Pobs[(size_t)r * HIDv + c] = v + bpost_in[c];
        });
    } else {             // pre = prev_actions @ WrnnT[:,256:]^T + b (row-masked)
        tile -= 2048;
        int bm0 = (tile & 127) << 7, bn0 = (tile >> 7) << 6;
        gemm_cp<true>(dyn, act - Av, Av, g_WrnnT + STOv, STOv + Av, Av, bm0, bn0, acc);
        epi_apply(bm0, bn0, acc, [&](int r, int c, float v) {
            g_pre[(size_t)r * HIDv + c] = v + brnn[c];
        });
    }
}

__global__ __launch_bounds__(256)
void rf_k(const float* __restrict__ h_o, const float* __restrict__ bprior_in) {
    extern __shared__ float dyn[];
    float acc[2][4][4];
    int tile = blockIdx.x;
    int bm0 = (tile & 127) << 7, bn0 = (tile >> 7) << 6;
    gemm_cp<false>(dyn, h_o, DETv, g_WpriorT, DETv, DETv, bm0, bn0, acc);
    epi_apply(bm0, bn0, acc, [&](int r, int c, float v) {
        g_Pobs[(size_t)r * HIDv + c] = fmaxf(v + bprior_in[c], 0.f);
    });
}

__global__ __launch_bounds__(256)
void ms_k(const float* __restrict__ bprior_ms,
          float* __restrict__ qm_o, float* __restrict__ qs_o) {
    extern __shared__ float dyn[];
    float acc[2][4][4];
    int tile = blockIdx.x;
    int bm0 = (tile & 127) << 7, bn0 = (tile >> 7) << 6;   // bn0 in 0..448
    gemm_cp<false>(dyn, g_Pobs, HIDv, g_WpriormsT, HIDv, HIDv, bm0, bn0, acc);
    if (bn0 < STOv) {
        epi_apply(bm0, bn0, acc, [&](int r, int c, float v) {
            qm_o[(size_t)r * STOv + c] = v + bprior_ms[c];
        });
    } else {
        epi_apply(bm0, bn0, acc, [&](int r, int c, float v) {
            qs_o[(size_t)r * STOv + (c - STOv)] = softplusf(v + bprior_ms[c]) + 0.1f;
        });
    }
}

// --------------------------- persistent scan kernel -------------------------
struct ScanArgs {
    const float* noise;
    const float* bih; const float* bhh;
    const float* bpost_ms;
    float* h_o; float* z_o; float* pm_o; float* ps_o;
    int nb;
};

__global__ __launch_bounds__(256)
void scan_k(ScanArgs a) {
    extern __shared__ float dyn[];
    const int nb = a.nb;
    float acc[2][4][4];

    for (int t = 0; t < Tv; t++) {
        // ---- P1: rnn = relu(z_prev @ Wz^T + pre_t)  (32 tiles, K=256)
        {
            const float* Az = t ? a.z_o + (size_t)(t - 1) * STOv : g_zero;
            int ldz = t ? Tv * STOv : 0;
            for (int tile = blockIdx.x; tile < 32; tile += nb) {
                int bm0 = (tile & 1) << 7, bn0 = (tile >> 1) << 6;
                gemm_cp<false>(dyn, Az, ldz, g_WrnnT, STOv + Av, STOv, bm0, bn0, acc);
                epi_apply(bm0, bn0, acc, [&](int r, int c, float v) {
                    v += g_pre[((size_t)r * Tv + t) * HIDv + c];
                    g_rnn[(size_t)r * HIDv + c] = fmaxf(v, 0.f);
                });
            }
        }
        gridbar(nb);

        // ---- P2: gh = h_prev@Whh^T + bhh (192 tiles, K=2048, LONG)
        //          gi = rnn@Wih^T + bih    (192 tiles, K=1024)
        {
            const float* Ah = t ? a.h_o + (size_t)(t - 1) * DETv : g_zero;
            int ldh = t ? Tv * DETv : 0;
            int split = (2 * nb) / 3;
            if ((int)blockIdx.x < split) {
                for (int tile = blockIdx.x; tile < 192; tile += split) {
                    int bm0 = (tile & 1) << 7, bn0 = (tile >> 1) << 6;
                    gemm_cp<false>(dyn, Ah, ldh, g_WhhR, DETv, DETv, bm0, bn0, acc);
                    epi_apply(bm0, bn0, acc, [&](int r, int c, float v) {
                        g_gh[(size_t)r * (3 * DETv) + c] = v + a.bhh[c];
                    });
                }
            } else {
                int bb = blockIdx.x - split, n2 = nb - split;
                for (int tile = bb; tile < 192; tile += n2) {
                    int bm0 = (tile & 1) << 7, bn0 = (tile >> 1) << 6;
                    gemm_cp<false>(dyn, g_rnn, HIDv, g_WihR, HIDv, HIDv, bm0, bn0, acc);
                    epi_apply(bm0, bn0, acc, [&](int r, int c, float v) {
                        g_gi[(size_t)r * (3 * DETv) + c] = v + a.bih[c];
                    });
                }
            }
        }
        gridbar(nb);

        // ---- P3: GRU elementwise -> h_t
        {
            const float* hp = t ? a.h_o + (size_t)(t - 1) * DETv : g_zero;
            int hps = t ? Tv * DETv : 0;
            for (int i = blockIdx.x * 256 + threadIdx.x; i < Bv * DETv; i += nb * 256) {
                int m = i >> 11, j = i & 2047;
                size_t base = (size_t)m * (3 * DETv);
                float r = sigmoidf(g_gi[base + j] + g_gh[base + j]);
                float u = sigmoidf(g_gi[base + DETv + j] + g_gh[base + DETv + j]);
                float n = tanhf(g_gi[base + 2 * DETv + j] + r * g_gh[base + 2 * DETv + j]);
                float hv = (1.f - u) * n + u * hp[(size_t)m * hps + j];
                a.h_o[((size_t)m * Tv + t) * DETv + j] = hv;
            }
        }
        gridbar(nb);

        // ---- P4a: pf split-K partials (128 tiles: 4ks x 32, K=512)
        for (int tile = blockIdx.x; tile < 128; tile += nb) {
            int ks = tile >> 5, rem = tile & 31;
            int bm0 = (rem & 1) << 7, bn0 = (rem >> 1) << 6;
            gemm_cp<false>(dyn, a.h_o + (size_t)t * DETv + ks * 512, Tv * DETv,
                           g_WpostT + ks * 512, DETv + Ev, 512, bm0, bn0, acc);
            epi_apply(bm0, bn0, acc, [&](int r, int c, float v) {
                g_p4[(size_t)ks * Bv * HIDv + (size_t)r * HIDv + c] = v;
            });
        }
        gridbar(nb);

        // ---- P4b: reduce + Pobs + relu -> pf
        for (int i = blockIdx.x * 256 + threadIdx.x; i < Bv * HIDv; i += nb * 256) {
            int m = i >> 10, j = i & 1023;
            float v = g_p4[i] + g_p4[(size_t)Bv * HIDv + i] +
                      g_p4[2 * (size_t)Bv * HIDv + i] + g_p4[3 * (size_t)Bv * HIDv + i];
            v += g_Pobs[((size_t)m * Tv + t) * HIDv + j];
            g_pf[i] = fmaxf(v, 0.f);
        }
        gridbar(nb);

        // ---- P5a: [pm|ps] split-K partials (64 tiles: 4ks x 2m x 8n, K=256)
        for (int tile = blockIdx.x; tile < 64; tile += nb) {
            int ks = tile >> 4, rem = tile & 15;
            int bm0 = (rem & 1) << 7, bn0 = (rem >> 1) << 6;
            gemm_cp<false>(dyn, g_pf + ks * 256, HIDv,
                           g_WpostmsT + ks * 256, HIDv, 256, bm0, bn0, acc);
            epi_apply(bm0, bn0, acc, [&](int r, int c, float v) {
                g_p5[(size_t)ks * Bv * (2 * STOv) + (size_t)r * (2 * STOv) + c] = v;
            });
        }
        gridbar(nb);

        // ---- P5b: pm, ps, z
        for (int i = blockIdx.x * 256 + threadIdx.x; i < Bv * STOv; i += nb * 256) {
            int m = i >> 8, j = i & 255;
            size_t b0 = (size_t)m * (2 * STOv);
            const size_t S = (size_t)Bv * (2 * STOv);
            float pm = g_p5[b0 + j] + g_p5[S + b0 + j] + g_p5[2 * S + b0 + j] +
                       g_p5[3 * S + b0 + j] + a.bpost_ms[j];
            float sr = g_p5[b0 + STOv + j] + g_p5[S + b0 + STOv + j] +
                       g_p5[2 * S + b0 + STOv + j] + g_p5[3 * S + b0 + STOv + j] +
                       a.bpost_ms[STOv + j];
            float ps = softplusf(sr) + 0.1f;
            size_t o = ((size_t)m * Tv + t) * STOv + j;
            a.pm_o[o] = pm;
            a.ps_o[o] = ps;
            a.z_o[o] = pm + ps * a.noise[o];
        }
        gridbar(nb);
    }
}

// ------------------------------- launch -------------------------------------
extern "C" void kernel_launch(void* const* d_in, const int* in_sizes, int n_in,
                              void* d_out, int out_size) {
    const float* obs      = (const float*)d_in[0];
    const float* act      = (const float*)d_in[1];
    const float* noise    = (const float*)d_in[4];
    const float* Wrnn     = (const float*)d_in[5];
    const float* brnn     = (const float*)d_in[6];
    const float* Wih      = (const float*)d_in[7];
    const float* Whh      = (const float*)d_in[8];
    const float* bih      = (const float*)d_in[9];
    const float* bhh      = (const float*)d_in[10];
    const float* Wpost_in = (const float*)d_in[11];
    const float* bpost_in = (const float*)d_in[12];
    const float* Wpost_ms = (const float*)d_in[13];
    const float* bpost_ms = (const float*)d_in[14];
    const float* Wprior_in= (const float*)d_in[15];
    const float* bprior_in= (const float*)d_in[16];
    const float* Wprior_ms= (const float*)d_in[17];
    const float* bprior_ms= (const float*)d_in[18];

    float* out  = (float*)d_out;
    float* h_o  = out;
    float* z_o  = h_o + (size_t)BTv * DETv;
    float* pm_o = z_o + (size_t)BTv * STOv;
    float* ps_o = pm_o + (size_t)BTv * STOv;
    float* qm_o = ps_o + (size_t)BTv * STOv;
    float* qs_o = qm_o + (size_t)BTv * STOv;

    cudaFuncSetAttribute(prep_k, cudaFuncAttributeMaxDynamicSharedMemorySize, DYN_SMEM);
    cudaFuncSetAttribute(rf_k,   cudaFuncAttributeMaxDynamicSharedMemorySize, DYN_SMEM);
    cudaFuncSetAttribute(ms_k,   cudaFuncAttributeMaxDynamicSharedMemorySize, DYN_SMEM);
    cudaFuncSetAttribute(scan_k, cudaFuncAttributeMaxDynamicSharedMemorySize, DYN_SMEM);

    float *WrnnT, *WpostT, *WpostmsT, *WpriorT, *WpriormsT, *WihR, *WhhR;
    cudaGetSymbolAddress((void**)&WrnnT,     g_WrnnT);
    cudaGetSymbolAddress((void**)&WpostT,    g_WpostT);
    cudaGetSymbolAddress((void**)&WpostmsT,  g_WpostmsT);
    cudaGetSymbolAddress((void**)&WpriorT,   g_WpriorT);
    cudaGetSymbolAddress((void**)&WpriormsT, g_WpriormsT);
    cudaGetSymbolAddress((void**)&WihR,      g_WihR);
    cudaGetSymbolAddress((void**)&WhhR,      g_WhhR);

    // 0) weight prep: transpose+round the [K,N] mats; round-copy the [N,K] mats
    transpose_k<<<dim3((STOv + Av) / 32, HIDv / 32), 256>>>(Wrnn, WrnnT, STOv + Av, HIDv);
    transpose_k<<<dim3((DETv + Ev) / 32, HIDv / 32), 256>>>(Wpost_in, WpostT, DETv + Ev, HIDv);
    transpose_k<<<dim3(HIDv / 32, (2 * STOv) / 32), 256>>>(Wpost_ms, WpostmsT, HIDv, 2 * STOv);
    transpose_k<<<dim3(DETv / 32, HIDv / 32), 256>>>(Wprior_in, WpriorT, DETv, HIDv);
    transpose_k<<<dim3(HIDv / 32, (2 * STOv) / 32), 256>>>(Wprior_ms, WpriormsT, HIDv, 2 * STOv);
    roundcopy_k<<<(3 * DETv * HIDv / 4 + 255) / 256, 256>>>(Wih, WihR, 3 * DETv * HIDv);
    roundcopy_k<<<(3 * DETv * DETv / 4 + 255) / 256, 256>>>(Whh, WhhR, 3 * DETv * DETv);

    // 1) batched precompute
    prep_k<<<4096, 256, DYN_SMEM>>>(obs, act, bpost_in, brnn);

    // 2) persistent scan
    int nsm = 0, maxb = 0;
    cudaDeviceGetAttribute(&nsm, cudaDevAttrMultiProcessorCount, 0);
    cudaOccupancyMaxActiveBlocksPerMultiprocessor(&maxb, scan_k, 256, DYN_SMEM);
    if (maxb > 2) maxb = 2;
    if (maxb < 1) maxb = 1;
    int nb = nsm * maxb;

    ScanArgs a;
    a.noise = noise;
    a.bih = bih; a.bhh = bhh;
    a.bpost_ms = bpost_ms;
    a.h_o = h_o; a.z_o = z_o; a.pm_o = pm_o; a.ps_o = ps_o;
    a.nb = nb;
    scan_k<<<nb, 256, DYN_SMEM>>>(a);

    // 3) batched prior
    rf_k<<<2048, 256, DYN_SMEM>>>(h_o, bprior_in);
    ms_k<<<1024, 256, DYN_SMEM>>>(bprior_ms, qm_o, qs_o);
}